// round 14
// baseline (speedup 1.0000x reference)
#include <cuda_runtime.h>
#include <cuda_bf16.h>
#include <cstdint>

#define BB 4
#define SS 2048
#define HH 16
#define DM 1024
#define PP (BB*SS)      // 8192 total positions
#define NW (DM/2)       // 512 bf16x2 k-words per 1024-dim

// ---------------------------------------------------------------------------
// Scratch. q/k: [pos][dword]. v: [b,h,d,pos-pair]. weights: [n][kw] packed.
// ---------------------------------------------------------------------------
__device__ uint32_t g_xh[PP*NW],  g_xl[PP*NW];          // x split  [pos][kw]
__device__ uint32_t g_wph[4][NW*DM], g_wpl[4][NW*DM];   // weights [n][kw]
__device__ uint32_t g_qh[2][PP*NW], g_ql[2][PP*NW];     // q(scaled), k
__device__ uint32_t g_vh[(PP/2)*DM], g_vl[(PP/2)*DM];   // v [b*16+h][d][s/2]
__device__ uint32_t g_ah[PP*NW],  g_al[PP*NW];          // attention out

// ---------------------------------------------------------------------------
// helpers
// ---------------------------------------------------------------------------
__device__ __forceinline__ void split2(float v0, float v1,
                                       uint32_t& hi, uint32_t& lo) {
    __nv_bfloat16 h0 = __float2bfloat16(v0);
    __nv_bfloat16 h1 = __float2bfloat16(v1);
    __nv_bfloat16 l0 = __float2bfloat16(v0 - __bfloat162float(h0));
    __nv_bfloat16 l1 = __float2bfloat16(v1 - __bfloat162float(h1));
    hi = (uint32_t)__bfloat16_as_ushort(h0) |
         ((uint32_t)__bfloat16_as_ushort(h1) << 16);
    lo = (uint32_t)__bfloat16_as_ushort(l0) |
         ((uint32_t)__bfloat16_as_ushort(l1) << 16);
}

__device__ __forceinline__ uint32_t smem_u32(const void* p) {
    uint32_t a;
    asm("{ .reg .u64 t; cvta.to.shared.u64 t, %1; cvt.u32.u64 %0, t; }"
        : "=r"(a) : "l"(p));
    return a;
}
__device__ __forceinline__ void cpa(uint32_t dst, const void* src) {
    asm volatile("cp.async.cg.shared.global [%0], [%1], 16;"
                 :: "r"(dst), "l"(src));
}
#define CP_COMMIT() asm volatile("cp.async.commit_group;" ::: "memory")
#define CP_WAIT1()  asm volatile("cp.async.wait_group 1;" ::: "memory")
#define CP_WAIT0()  asm volatile("cp.async.wait_group 0;" ::: "memory")

__device__ __forceinline__ void ldsm4(uint32_t& r0, uint32_t& r1,
                                      uint32_t& r2, uint32_t& r3, uint32_t a) {
    asm volatile("ldmatrix.sync.aligned.m8n8.x4.shared.b16 {%0,%1,%2,%3}, [%4];"
                 : "=r"(r0), "=r"(r1), "=r"(r2), "=r"(r3) : "r"(a));
}

// D += A * B  (m16n8k16, bf16 in, fp32 accum)
__device__ __forceinline__ void mma16(float* c, const uint32_t* a,
                                      uint32_t b0, uint32_t b1) {
    asm volatile(
        "mma.sync.aligned.m16n8k16.row.col.f32.bf16.bf16.f32 "
        "{%0,%1,%2,%3}, {%4,%5,%6,%7}, {%8,%9}, {%0,%1,%2,%3};"
        : "+f"(c[0]), "+f"(c[1]), "+f"(c[2]), "+f"(c[3])
        : "r"(a[0]), "r"(a[1]), "r"(a[2]), "r"(a[3]), "r"(b0), "r"(b1));
}

// ---------------------------------------------------------------------------
// Prep: split x; weights -> [n][kw] split layout via smem-tiled transpose
// ---------------------------------------------------------------------------
__global__ __launch_bounds__(256) void prep_x(const float* __restrict__ x) {
    const size_t i = (size_t)blockIdx.x * 256 + threadIdx.x;
    float2 v = *(const float2*)(x + 2 * i);
    split2(v.x, v.y, g_xh[i], g_xl[i]);
}

__global__ __launch_bounds__(256) void prep_w(
    const float* __restrict__ Qw, const float* __restrict__ Kw,
    const float* __restrict__ Vw, const float* __restrict__ Ow) {
    __shared__ float sm[128][68];
    const int which = blockIdx.x, kt = blockIdx.y, nt = blockIdx.z;
    const float* W = (which == 0) ? Qw : (which == 1) ? Kw :
                     (which == 2) ? Vw : Ow;
    const int k0 = kt * 128, n0 = nt * 64;
    const int tid = threadIdx.x;
    // load 128 k-rows x 64 n cols, coalesced
    {
        const int r = tid >> 1, cseg = (tid & 1) * 32;
        const float* src = (which < 3)
            ? W + (size_t)nt * (1024 * 64) + (size_t)(k0 + r) * 64 + cseg
            : W + (size_t)(k0 + r) * 1024 + n0 + cseg;
        #pragma unroll
        for (int j = 0; j < 8; j++)
            *(float4*)&sm[r][cseg + j * 4] = *(const float4*)(src + j * 4);
    }
    __syncthreads();
    // write 64 n rows x 64 kwords, split+packed
    {
        const int nl = tid & 63, kw0 = (tid >> 6) * 16;
        uint32_t wh[16], wl[16];
        #pragma unroll
        for (int j = 0; j < 16; j++)
            split2(sm[2 * (kw0 + j)][nl], sm[2 * (kw0 + j) + 1][nl],
                   wh[j], wl[j]);
        uint32_t* dh = g_wph[which] + (size_t)(n0 + nl) * NW + kt * 64 + kw0;
        uint32_t* dl = g_wpl[which] + (size_t)(n0 + nl) * NW + kt * 64 + kw0;
        #pragma unroll
        for (int j = 0; j < 4; j++) {
            *(uint4*)(dh + j * 4) = make_uint4(wh[4*j], wh[4*j+1], wh[4*j+2], wh[4*j+3]);
            *(uint4*)(dl + j * 4) = make_uint4(wl[4*j], wl[4*j+1], wl[4*j+2], wl[4*j+3]);
        }
    }
}

// ===========================================================================
// GEMM bf16x3, cp.async + ldmatrix. C tile 128x128, k-step 16.
// A smem [m 128][pitch 12]; B smem [n 128][pitch 12]; both ldmatrix-friendly.
// ===========================================================================
#define APITCH 12
#define ABUF (128 * APITCH * 4)

__global__ __launch_bounds__(256, 2) void gemm_bf16(
    const float* __restrict__ B0, const float* __restrict__ B1,
    const float* __restrict__ B2,
    float* __restrict__ oout, int mode)
{
    __shared__ __align__(16) uint32_t Ah[2][128][APITCH], Al[2][128][APITCH];
    __shared__ __align__(16) uint32_t Bh[2][128][APITCH], Bl[2][128][APITCH];

    const int tid  = threadIdx.x;
    const int lane = tid & 31, wid = tid >> 5;
    const int wm = wid & 1, wn = wid >> 1;
    const int g  = lane >> 2, qd = lane & 3;
    const int p0 = blockIdx.x * 128, nt = blockIdx.y;

    const int which = (mode == 0) ? (nt >> 3) : 3;
    const int cw    = (mode == 0) ? (nt & 7) * 128 : nt * 128;
    const float* bias = (mode == 0)
        ? ((which == 0) ? B0 : (which == 1) ? B1 : B2) : B0;
    const uint32_t* Awh = (mode == 0) ? g_xh : g_ah;
    const uint32_t* Awl = (mode == 0) ? g_xl : g_al;
    const uint32_t* wph = g_wph[which];
    const uint32_t* wpl = g_wpl[which];

    // producer coords: both A and B are 128 rows x 8 kwords (2 x 16B chunks)
    const int ar = tid >> 1, ac4 = (tid & 1) * 4;
    const uint32_t dAh = smem_u32(&Ah[0][ar][ac4]);
    const uint32_t dAl = smem_u32(&Al[0][ar][ac4]);
    const uint32_t dBh = smem_u32(&Bh[0][ar][ac4]);
    const uint32_t dBl = smem_u32(&Bl[0][ar][ac4]);

    auto issue = [&](int it, int buf) {
        const size_t aw = (size_t)(p0 + ar) * NW + it * 8 + ac4;
        const size_t bw = (size_t)(cw + ar) * NW + it * 8 + ac4;
        cpa(dAh + buf * ABUF, Awh + aw);
        cpa(dAl + buf * ABUF, Awl + aw);
        cpa(dBh + buf * ABUF, wph + bw);
        cpa(dBl + buf * ABUF, wpl + bw);
        CP_COMMIT();
    };

    // ldmatrix lane constants
    const int larow = lane & 15, lacol = (lane >> 4) * 4;            // A m16k16
    const int lbrow = (lane >> 4) * 8 + (lane & 7);                  // B n8k16 x2
    const int lbcol = ((lane >> 3) & 1) * 4;
    const uint32_t aBh = smem_u32(Ah), aBl = smem_u32(Al);
    const uint32_t bBh = smem_u32(Bh), bBl = smem_u32(Bl);

    float c[4][4][4] = {};

    issue(0, 0);
    for (int it = 0; it < 64; it++) {
        const int buf = it & 1;
        if (it < 63) { issue(it + 1, buf ^ 1); CP_WAIT1(); }
        else         { CP_WAIT0(); }
        __syncthreads();

        uint32_t fah[4][4], fal[4][4], fbh[4][2], fbl[4][2];
        #pragma unroll
        for (int mt = 0; mt < 4; mt++) {
            const uint32_t off = (uint32_t)buf * ABUF +
                ((wm * 64 + mt * 16 + larow) * APITCH + lacol) * 4;
            ldsm4(fah[mt][0], fah[mt][1], fah[mt][2], fah[mt][3], aBh + off);
            ldsm4(fal[mt][0], fal[mt][1], fal[mt][2], fal[mt][3], aBl + off);
        }
        #pragma unroll
        for (int p = 0; p < 2; p++) {
            const uint32_t off = (uint32_t)buf * ABUF +
                ((wn * 32 + p * 16 + lbrow) * APITCH + lbcol) * 4;
            ldsm4(fbh[2*p][0], fbh[2*p][1], fbh[2*p+1][0], fbh[2*p+1][1], bBh + off);
            ldsm4(fbl[2*p][0], fbl[2*p][1], fbl[2*p+1][0], fbl[2*p+1][1], bBl + off);
        }
        #pragma unroll
        for (int mt = 0; mt < 4; mt++)
            #pragma unroll
            for (int nn = 0; nn < 4; nn++) {
                mma16(c[mt][nn], fah[mt], fbh[nn][0], fbh[nn][1]);   // hi*hi
                mma16(c[mt][nn], fah[mt], fbl[nn][0], fbl[nn][1]);   // hi*lo
                mma16(c[mt][nn], fal[mt], fbh[nn][0], fbh[nn][1]);   // lo*hi
            }
        __syncthreads();
    }

    // ---- Epilogues ----
    if (mode == 1) {
        #pragma unroll
        for (int mt = 0; mt < 4; mt++) {
            const int row = p0 + wm * 64 + mt * 16 + g;
            #pragma unroll
            for (int nn = 0; nn < 4; nn++) {
                const int col = cw + wn * 32 + nn * 8 + 2 * qd;
                const float2 bv = *(const float2*)(bias + col);
                float2 v0, v1;
                v0.x = c[mt][nn][0] + bv.x; v0.y = c[mt][nn][1] + bv.y;
                v1.x = c[mt][nn][2] + bv.x; v1.y = c[mt][nn][3] + bv.y;
                *(float2*)(oout + (size_t)row * DM + col) = v0;
                *(float2*)(oout + (size_t)(row + 8) * DM + col) = v1;
            }
        }
    } else if (which == 2) {
        // V: pair adjacent positions via shfl; store [b,h,d,pos-pair]
        #pragma unroll
        for (int mt = 0; mt < 4; mt++) {
            const int row = p0 + wm * 64 + mt * 16 + g;
            #pragma unroll
            for (int nn = 0; nn < 4; nn++) {
                const int col = cw + wn * 32 + nn * 8 + 2 * qd;
                const float2 bv = *(const float2*)(bias + col);
                float o0 = c[mt][nn][0] + bv.x, o1 = c[mt][nn][1] + bv.y;
                float o2 = c[mt][nn][2] + bv.x, o3 = c[mt][nn][3] + bv.y;
                float p0v = __shfl_xor_sync(0xffffffffu, o0, 4);
                float p1v = __shfl_xor_sync(0xffffffffu, o1, 4);
                float p2v = __shfl_xor_sync(0xffffffffu, o2, 4);
                float p3v = __shfl_xor_sync(0xffffffffu, o3, 4);
                if ((g & 1) == 0) {
                    const int bb = row >> 11, s_ = row & 2047;
                    const int hc = col >> 6, dc = col & 63;
                    const size_t w0 =
                        ((size_t)(bb * HH + hc) * 64 + dc) * (SS/2) + (s_ >> 1);
                    uint32_t h0, l0, h1, l1;
                    split2(o0, p0v, h0, l0);          // d = dc
                    split2(o1, p1v, h1, l1);          // d = dc+1
                    g_vh[w0] = h0; g_vl[w0] = l0;
                    g_vh[w0 + SS/2] = h1; g_vl[w0 + SS/2] = l1;
                    split2(o2, p2v, h0, l0);          // row+8 -> pair idx +4
                    split2(o3, p3v, h1, l1);
                    g_vh[w0 + 4] = h0; g_vl[w0 + 4] = l0;
                    g_vh[w0 + SS/2 + 4] = h1; g_vl[w0 + SS/2 + 4] = l1;
                }
            }
        }
    } else {
        const float sc = (which == 0) ? 0.125f : 1.0f;
        uint32_t* oh = g_qh[which];
        uint32_t* ol = g_ql[which];
        #pragma unroll
        for (int mt = 0; mt < 4; mt++) {
            const int row = p0 + wm * 64 + mt * 16 + g;
            #pragma unroll
            for (int nn = 0; nn < 4; nn++) {
                const int col = cw + wn * 32 + nn * 8 + 2 * qd;
                const float2 bv = *(const float2*)(bias + col);
                const size_t w0 = (size_t)row * NW + (col >> 1);
                const size_t w1 = (size_t)(row + 8) * NW + (col >> 1);
                split2((c[mt][nn][0] + bv.x) * sc, (c[mt][nn][1] + bv.y) * sc,
                       oh[w0], ol[w0]);
                split2((c[mt][nn][2] + bv.x) * sc, (c[mt][nn][3] + bv.y) * sc,
                       oh[w1], ol[w1]);
            }
        }
    }
}

// ===========================================================================
// Flash attention bf16x3 + ldmatrix. q-tile 128, 8 warps, cp.async dbl-buffer.
// K smem [kpos 64][pitch 36] (dwords); V smem [d 64][pitch 36] (kwords).
// ===========================================================================
#define KPP 36
#define VP  36
#define KSTG (64 * KPP)
#define VSTG (64 * VP)
#define ATTN_SMEM ((2 * 2 * KSTG + 2 * 2 * VSTG) * 4)   // 73728 B

__global__ __launch_bounds__(256, 2) void attn_bf16()
{
    extern __shared__ __align__(16) uint32_t dsm[];
    uint32_t* KH = dsm;                   // [2][64][KPP]
    uint32_t* KL = KH + 2 * KSTG;
    uint32_t* VH = KL + 2 * KSTG;         // [2][64][VP]
    uint32_t* VL = VH + 2 * VSTG;

    const int tid = threadIdx.x, lane = tid & 31, w = tid >> 5;
    const int g = lane >> 2, qd = lane & 3;
    const int qt = blockIdx.x, bh = blockIdx.y;
    const int b = bh >> 4, h = bh & 15;
    const int q0 = qt * 128;
    const int kr = tid >> 2, kq = (tid & 3) * 8;    // loader: row, word offset

    const uint32_t dK = smem_u32(KH + kr * KPP + kq);
    const uint32_t dV = smem_u32(VH + kr * VP + kq);
    const size_t vbase = (size_t)(b * HH + h) * 64 * (SS/2);

    auto issue = [&](int kt, int s) {
        const int k0 = kt * 64;
        const size_t rw = (size_t)(b * SS + k0 + kr) * NW + h * 32 + kq;
        const uint32_t ks = dK + s * (KSTG * 4);
        cpa(ks,      g_qh[1] + rw);
        cpa(ks + 16, g_qh[1] + rw + 4);
        cpa(ks + 2 * KSTG * 4,      g_ql[1] + rw);
        cpa(ks + 2 * KSTG * 4 + 16, g_ql[1] + rw + 4);
        const size_t vw = vbase + (size_t)kr * (SS/2) + (k0 >> 1) + kq;
        const uint32_t vs = dV + s * (VSTG * 4);
        cpa(vs,      g_vh + vw);
        cpa(vs + 16, g_vh + vw + 4);
        cpa(vs + 2 * VSTG * 4,      g_vl + vw);
        cpa(vs + 2 * VSTG * 4 + 16, g_vl + vw + 4);
        CP_COMMIT();
    };

    issue(0, 0);

    // ---- Q fragments straight from global ----
    uint32_t qh[4][4], ql[4][4];
    {
        const size_t rw = (size_t)(b * SS + q0 + w * 16 + g) * NW + h * 32;
        const uint32_t* ph = g_qh[0] + rw;
        const uint32_t* pl = g_ql[0] + rw;
        #pragma unroll
        for (int t = 0; t < 4; t++) {
            qh[t][0] = ph[t * 8 + qd];       qh[t][1] = ph[8 * NW + t * 8 + qd];
            qh[t][2] = ph[t * 8 + qd + 4];   qh[t][3] = ph[8 * NW + t * 8 + qd + 4];
            ql[t][0] = pl[t * 8 + qd];       ql[t][1] = pl[8 * NW + t * 8 + qd];
            ql[t][2] = pl[t * 8 + qd + 4];   ql[t][3] = pl[8 * NW + t * 8 + qd + 4];
        }
    }

    // ldmatrix lane constants (shared by K and V frag loads)
    const int lmrow = (lane >> 4) * 8 + (lane & 7);
    const int lmcol = ((lane >> 3) & 1) * 4;
    const uint32_t kBh = smem_u32(KH), kBl = smem_u32(KL);
    const uint32_t vBh = smem_u32(VH), vBl = smem_u32(VL);

    float m0 = -1e30f, m1 = -1e30f, l0s = 0.f, l1s = 0.f;
    float acc[8][4] = {};

    const int nkt = 2 * qt + 2;
    for (int kt = 0; kt < nkt; kt++) {
        const int s = kt & 1;
        const int k0 = kt * 64;
        if (kt + 1 < nkt) { issue(kt + 1, s ^ 1); CP_WAIT1(); }
        else              { CP_WAIT0(); }
        __syncthreads();

        if (k0 <= q0 + w * 16 + 15) {
            // ---- S = Q K^T (Q pre-scaled), 3-term, ldmatrix frags ----
            float c[8][4] = {};
            #pragma unroll
            for (int t = 0; t < 4; t++) {
                #pragma unroll
                for (int p = 0; p < 4; p++) {
                    const uint32_t off = (uint32_t)s * (KSTG * 4) +
                        ((p * 16 + lmrow) * KPP + t * 8 + lmcol) * 4;
                    uint32_t b0, b1, b2, b3, e0, e1, e2, e3;
                    ldsm4(b0, b1, b2, b3, kBh + off);
                    ldsm4(e0, e1, e2, e3, kBl + off);
                    mma16(c[2*p],   qh[t], b0, b1);
                    mma16(c[2*p],   qh[t], e0, e1);
                    mma16(c[2*p],   ql[t], b0, b1);
                    mma16(c[2*p+1], qh[t], b2, b3);
                    mma16(c[2*p+1], qh[t], e2, e3);
                    mma16(c[2*p+1], ql[t], b2, b3);
                }
            }

            // ---- causal mask ----
            if (k0 + 63 > q0 + w * 16) {
                const int qg0 = q0 + w * 16 + g, qg1 = qg0 + 8;
                #pragma unroll
                for (int nt = 0; nt < 8; nt++) {
                    const int c0 = k0 + nt * 8 + 2 * qd;
                    if (c0     > qg0) c[nt][0] = -100000.f;
                    if (c0 + 1 > qg0) c[nt][1] = -100000.f;
                    if (c0     > qg1) c[nt][2] = -100000.f;
                    if (c0 + 1 > qg1) c[nt][3] = -100000.f;
                }
            }

            // ---- online softmax ----
            float rmax0 = -1e30f, rmax1 = -1e30f;
            #pragma unroll
            for (int nt = 0; nt < 8; nt++) {
                rmax0 = fmaxf(rmax0, fmaxf(c[nt][0], c[nt][1]));
                rmax1 = fmaxf(rmax1, fmaxf(c[nt][2], c[nt][3]));
            }
            rmax0 = fmaxf(rmax0, __shfl_xor_sync(0xffffffffu, rmax0, 1));
            rmax0 = fmaxf(rmax0, __shfl_xor_sync(0xffffffffu, rmax0, 2));
            rmax1 = fmaxf(rmax1, __shfl_xor_sync(0xffffffffu, rmax1, 1));
            rmax1 = fmaxf(rmax1, __shfl_xor_sync(0xffffffffu, rmax1, 2));

            const float nm0 = fmaxf(m0, rmax0), nm1 = fmaxf(m1, rmax1);
            const float f0 = __expf(m0 - nm0), f1 = __expf(m1 - nm1);
            float s0 = 0.f, s1 = 0.f;
            #pragma unroll
            for (int nt = 0; nt < 8; nt++) {
                c[nt][0] = __expf(c[nt][0] - nm0); s0 += c[nt][0];
                c[nt][1] = __expf(c[nt][1] - nm0); s0 += c[nt][1];
                c[nt][2] = __expf(c[nt][2] - nm1); s1 += c[nt][2];
                c[nt][3] = __expf(c[nt][3] - nm1); s1 += c[nt][3];
            }
            s0 += __shfl_xor_sync(0xffffffffu, s0, 1);
            s0 += __shfl_xor_sync(0xffffffffu, s0, 2);
            s1 += __shfl_xor_sync(0xffffffffu, s1, 1);
            s1 += __shfl_xor_sync(0xffffffffu, s1, 2);
            l0s = l0s * f0 + s0; l1s = l1s * f1 + s1;
            m0 = nm0; m1 = nm1;
            #pragma unroll
            for (int dt = 0; dt < 8; dt++) {
                acc[dt][0] *= f0; acc[dt][1] *= f0;
                acc[dt][2] *= f1; acc[dt][3] *= f1;
            }

            // ---- PV, 3-term; A-frag = packed C-frag, V frags ldmatrix ----
            #pragma unroll
            for (int t = 0; t < 4; t++) {
                uint32_t ah[4], al[4];
                split2(c[2 * t][0],     c[2 * t][1],     ah[0], al[0]);
                split2(c[2 * t][2],     c[2 * t][3],     ah[1], al[1]);
                split2(c[2 * t + 1][0], c[2 * t + 1][1], ah[2], al[2]);
                split2(c[2 * t + 1][2], c[2 * t + 1][3], ah[3], al[3]);
                #pragma unroll
                for (int p = 0; p < 4; p++) {
                    const uint32_t off = (uint32_t)s * (VSTG * 4) +
                        ((p * 16 + lmrow) * VP + t * 8 + lmcol) * 4;
                    uint32_t b0, b1, b2, b3, e0, e1, e2, e3;
                    ldsm4(b0, b1, b2, b3, vBh + off);
                    ldsm4(e0, e1, e2, e3, vBl + off);
                    mma16(acc[2*p],   ah, b0, b1);
                    mma16(acc[2*p],   ah, e0, e1);
                    mma16(acc[2*p],   al, b0, b1);
                    mma16(acc[2*p+1], ah, b2, b3);
                    mma16(acc[2*p+1], ah, e2, e3);
                    mma16(acc[2*p+1], al, b2, b3);
                }
            }
        }
        __syncthreads();   // all reads of stage s done before re-issue into it
    }

    // ---- normalize + write split hi/lo ----
    const float inv0 = 1.f / l0s, inv1 = 1.f / l1s;
    const size_t r0w = (size_t)(b * SS + q0 + w * 16 + g) * NW + h * 32;
    #pragma unroll
    for (int dt = 0; dt < 8; dt++) {
        const size_t w0 = r0w + dt * 4 + qd;
        const size_t w1 = w0 + 8 * NW;
        split2(acc[dt][0] * inv0, acc[dt][1] * inv0, g_ah[w0], g_al[w0]);
        split2(acc[dt][2] * inv1, acc[dt][3] * inv1, g_ah[w1], g_al[w1]);
    }
}

extern "C" void kernel_launch(void* const* d_in, const int* in_sizes, int n_in,
                              void* d_out, int out_size)
{
    const float* x  = (const float*)d_in[0];
    const float* Qw = (const float*)d_in[1];
    const float* Qb = (const float*)d_in[2];
    const float* Kw = (const float*)d_in[3];
    const float* Kb = (const float*)d_in[4];
    const float* Vw = (const float*)d_in[5];
    const float* Vb = (const float*)d_in[6];
    const float* Ow = (const float*)d_in[7];
    const float* Ob = (const float*)d_in[8];
    float* out = (float*)d_out;

    cudaFuncSetAttribute(attn_bf16,
                         cudaFuncAttributeMaxDynamicSharedMemorySize, ATTN_SMEM);

    prep_x<<<(PP * NW) / 256, 256>>>(x);
    prep_w<<<dim3(4, 8, 16), 256>>>(Qw, Kw, Vw, Ow);

    dim3 gq(PP / 128, 24);
    gemm_bf16<<<gq, 256>>>(Qb, Kb, Vb, nullptr, 0);

    dim3 ga(SS / 128, BB * HH);
    attn_bf16<<<ga, 256, ATTN_SMEM>>>();

    dim3 go(PP / 128, DM / 128);
    gemm_bf16<<<go, 256>>>(Ob, nullptr, nullptr, out, 1);
}

// round 15
// speedup vs baseline: 1.0838x; 1.0838x over previous
#include <cuda_runtime.h>
#include <cuda_bf16.h>
#include <cstdint>

#define BB 4
#define SS 2048
#define HH 16
#define DM 1024
#define PP (BB*SS)      // 8192 total positions
#define NW (DM/2)       // 512 bf16x2 words per row

// ---------------------------------------------------------------------------
// Scratch: bf16 hi/lo word pairs. x/q/k/attn: [pos][kword]. weights: [kw][n].
// v: [b*16+h][d][pos-pair] (transposed for ldmatrix PV fragments).
// ---------------------------------------------------------------------------
__device__ uint32_t g_xh[PP*NW],  g_xl[PP*NW];
__device__ uint32_t g_wph[4][NW*DM], g_wpl[4][NW*DM];
__device__ uint32_t g_qh[2][PP*NW], g_ql[2][PP*NW];     // q(scaled), k
__device__ uint32_t g_vh[(PP/2)*DM], g_vl[(PP/2)*DM];   // v [b*16+h][d][s/2]
__device__ uint32_t g_ah[PP*NW],  g_al[PP*NW];

// ---------------------------------------------------------------------------
// helpers
// ---------------------------------------------------------------------------
__device__ __forceinline__ void split2(float v0, float v1,
                                       uint32_t& hi, uint32_t& lo) {
    __nv_bfloat16 h0 = __float2bfloat16(v0);
    __nv_bfloat16 h1 = __float2bfloat16(v1);
    __nv_bfloat16 l0 = __float2bfloat16(v0 - __bfloat162float(h0));
    __nv_bfloat16 l1 = __float2bfloat16(v1 - __bfloat162float(h1));
    hi = (uint32_t)__bfloat16_as_ushort(h0) |
         ((uint32_t)__bfloat16_as_ushort(h1) << 16);
    lo = (uint32_t)__bfloat16_as_ushort(l0) |
         ((uint32_t)__bfloat16_as_ushort(l1) << 16);
}

__device__ __forceinline__ uint32_t smem_u32(const void* p) {
    uint32_t a;
    asm("{ .reg .u64 t; cvta.to.shared.u64 t, %1; cvt.u32.u64 %0, t; }"
        : "=r"(a) : "l"(p));
    return a;
}
__device__ __forceinline__ void cpa(uint32_t dst, const void* src) {
    asm volatile("cp.async.cg.shared.global [%0], [%1], 16;"
                 :: "r"(dst), "l"(src));
}
#define CP_COMMIT() asm volatile("cp.async.commit_group;" ::: "memory")
#define CP_WAIT1()  asm volatile("cp.async.wait_group 1;" ::: "memory")
#define CP_WAIT0()  asm volatile("cp.async.wait_group 0;" ::: "memory")

__device__ __forceinline__ void ldsm4(uint32_t& r0, uint32_t& r1,
                                      uint32_t& r2, uint32_t& r3, uint32_t a) {
    asm volatile("ldmatrix.sync.aligned.m8n8.x4.shared.b16 {%0,%1,%2,%3}, [%4];"
                 : "=r"(r0), "=r"(r1), "=r"(r2), "=r"(r3) : "r"(a));
}

// D += A * B  (m16n8k16, bf16 in, fp32 accum)
__device__ __forceinline__ void mma16(float* c, const uint32_t* a,
                                      uint32_t b0, uint32_t b1) {
    asm volatile(
        "mma.sync.aligned.m16n8k16.row.col.f32.bf16.bf16.f32 "
        "{%0,%1,%2,%3}, {%4,%5,%6,%7}, {%8,%9}, {%0,%1,%2,%3};"
        : "+f"(c[0]), "+f"(c[1]), "+f"(c[2]), "+f"(c[3])
        : "r"(a[0]), "r"(a[1]), "r"(a[2]), "r"(a[3]), "r"(b0), "r"(b1));
}

// ---------------------------------------------------------------------------
// Prep: split x; split+transpose weights into [kw][n] packed layout
// ---------------------------------------------------------------------------
__global__ __launch_bounds__(256) void prep_x(const float* __restrict__ x) {
    const size_t i = (size_t)blockIdx.x * 256 + threadIdx.x;
    float2 v = *(const float2*)(x + 2 * i);
    split2(v.x, v.y, g_xh[i], g_xl[i]);
}

__global__ __launch_bounds__(256) void prep_w(
    const float* __restrict__ Qw, const float* __restrict__ Kw,
    const float* __restrict__ Vw, const float* __restrict__ Ow) {
    const int i = blockIdx.x * 256 + threadIdx.x;
    const int which = i >> 19;                       // NW*DM = 2^19
    const int rem = i & ((NW * DM) - 1);
    const int kw = rem >> 10, n = rem & 1023;
    float v0, v1;
    if (which < 3) {
        const float* W = (which == 0) ? Qw : (which == 1) ? Kw : Vw;
        const int h = n >> 6, d = n & 63;
        const float* p = W + ((size_t)h * DM + 2 * kw) * 64 + d;
        v0 = p[0]; v1 = p[64];
    } else {
        const float* p = Ow + (size_t)(2 * kw) * DM + n;
        v0 = p[0]; v1 = p[DM];
    }
    split2(v0, v1, ((uint32_t*)g_wph)[i], ((uint32_t*)g_wpl)[i]);
}

// ===========================================================================
// GEMM bf16x3, cp.async double-buffered (R13 configuration: scalar frag
// loads, lo-A reload keeps regs under the cap). C tile 128x128, k-step 16.
//   mode 0 (QKV): which 0 -> q (scaled 1/8); 1 -> k; 2 -> v transposed store
//   mode 1 (O):   A = g_ah/al, B = g_wp[3] -> fp32 d_out + bias
// ===========================================================================
#define APITCH 12
#define BPITCH 136

__global__ __launch_bounds__(256, 2) void gemm_bf16(
    const float* __restrict__ B0, const float* __restrict__ B1,
    const float* __restrict__ B2,
    float* __restrict__ oout, int mode)
{
    __shared__ __align__(16) uint32_t Ah[2][128][APITCH], Al[2][128][APITCH];
    __shared__ __align__(16) uint32_t Bh[2][8][BPITCH],   Bl[2][8][BPITCH];

    const int tid  = threadIdx.x;
    const int lane = tid & 31, wid = tid >> 5;
    const int wm = wid & 1, wn = wid >> 1;
    const int g  = lane >> 2, qd = lane & 3;
    const int p0 = blockIdx.x * 128, nt = blockIdx.y;

    const int which = (mode == 0) ? (nt >> 3) : 3;
    const int cw    = (mode == 0) ? (nt & 7) * 128 : nt * 128;
    const float* bias = (mode == 0)
        ? ((which == 0) ? B0 : (which == 1) ? B1 : B2) : B0;
    const uint32_t* Awh = (mode == 0) ? g_xh : g_ah;
    const uint32_t* Awl = (mode == 0) ? g_xl : g_al;
    const uint32_t* wph = g_wph[which];
    const uint32_t* wpl = g_wpl[which];

    // producer coords
    const int ar = tid >> 1, ah4 = (tid & 1) * 4;
    const int bkw = tid >> 5, bn4 = (tid & 31) * 4;
    const uint32_t dAh = smem_u32(&Ah[0][ar][ah4]);
    const uint32_t dAl = smem_u32(&Al[0][ar][ah4]);
    const uint32_t dBh = smem_u32(&Bh[0][bkw][bn4]);
    const uint32_t dBl = smem_u32(&Bl[0][bkw][bn4]);
    const uint32_t abuf = 128 * APITCH * 4, bbuf = 8 * BPITCH * 4;

    auto issue = [&](int it, int buf) {
        const size_t aw = (size_t)(p0 + ar) * NW + it * 8 + ah4;
        const size_t bw = (size_t)(it * 8 + bkw) * DM + cw + bn4;
        cpa(dAh + buf * abuf, Awh + aw);
        cpa(dAl + buf * abuf, Awl + aw);
        cpa(dBh + buf * bbuf, wph + bw);
        cpa(dBl + buf * bbuf, wpl + bw);
        CP_COMMIT();
    };

    float c[4][4][4] = {};

    issue(0, 0);
    for (int it = 0; it < 64; it++) {
        const int buf = it & 1;
        if (it < 63) { issue(it + 1, buf ^ 1); CP_WAIT1(); }
        else         { CP_WAIT0(); }
        __syncthreads();

        uint32_t fa[4][4], fbh[4][2], fbl[4][2];
        #pragma unroll
        for (int mt = 0; mt < 4; mt++) {
            const int r = wm * 64 + mt * 16 + g;
            fa[mt][0] = Ah[buf][r][qd];
            fa[mt][1] = Ah[buf][r + 8][qd];
            fa[mt][2] = Ah[buf][r][qd + 4];
            fa[mt][3] = Ah[buf][r + 8][qd + 4];
        }
        #pragma unroll
        for (int nn = 0; nn < 4; nn++) {
            const int ncol = wn * 32 + nn * 8 + g;
            fbh[nn][0] = Bh[buf][qd][ncol];
            fbh[nn][1] = Bh[buf][qd + 4][ncol];
            fbl[nn][0] = Bl[buf][qd][ncol];
            fbl[nn][1] = Bl[buf][qd + 4][ncol];
        }
        #pragma unroll
        for (int mt = 0; mt < 4; mt++)
            #pragma unroll
            for (int nn = 0; nn < 4; nn++) {
                mma16(c[mt][nn], fa[mt], fbh[nn][0], fbh[nn][1]);   // hi*hi
                mma16(c[mt][nn], fa[mt], fbl[nn][0], fbl[nn][1]);   // hi*lo
            }
        #pragma unroll
        for (int mt = 0; mt < 4; mt++) {
            const int r = wm * 64 + mt * 16 + g;
            fa[mt][0] = Al[buf][r][qd];
            fa[mt][1] = Al[buf][r + 8][qd];
            fa[mt][2] = Al[buf][r][qd + 4];
            fa[mt][3] = Al[buf][r + 8][qd + 4];
        }
        #pragma unroll
        for (int mt = 0; mt < 4; mt++)
            #pragma unroll
            for (int nn = 0; nn < 4; nn++)
                mma16(c[mt][nn], fa[mt], fbh[nn][0], fbh[nn][1]);   // lo*hi
        __syncthreads();
    }

    // ---- Epilogues ----
    if (mode == 1) {
        #pragma unroll
        for (int mt = 0; mt < 4; mt++) {
            const int row = p0 + wm * 64 + mt * 16 + g;
            #pragma unroll
            for (int nn = 0; nn < 4; nn++) {
                const int col = cw + wn * 32 + nn * 8 + 2 * qd;
                const float2 bv = *(const float2*)(bias + col);
                float2 v0, v1;
                v0.x = c[mt][nn][0] + bv.x; v0.y = c[mt][nn][1] + bv.y;
                v1.x = c[mt][nn][2] + bv.x; v1.y = c[mt][nn][3] + bv.y;
                *(float2*)(oout + (size_t)row * DM + col) = v0;
                *(float2*)(oout + (size_t)(row + 8) * DM + col) = v1;
            }
        }
    } else if (which == 2) {
        // V: pair adjacent positions via shfl; store [b,h,d,pos-pair]
        #pragma unroll
        for (int mt = 0; mt < 4; mt++) {
            const int row = p0 + wm * 64 + mt * 16 + g;
            #pragma unroll
            for (int nn = 0; nn < 4; nn++) {
                const int col = cw + wn * 32 + nn * 8 + 2 * qd;
                const float2 bv = *(const float2*)(bias + col);
                float o0 = c[mt][nn][0] + bv.x, o1 = c[mt][nn][1] + bv.y;
                float o2 = c[mt][nn][2] + bv.x, o3 = c[mt][nn][3] + bv.y;
                float p0v = __shfl_xor_sync(0xffffffffu, o0, 4);
                float p1v = __shfl_xor_sync(0xffffffffu, o1, 4);
                float p2v = __shfl_xor_sync(0xffffffffu, o2, 4);
                float p3v = __shfl_xor_sync(0xffffffffu, o3, 4);
                if ((g & 1) == 0) {
                    const int bb = row >> 11, s_ = row & 2047;
                    const int hc = col >> 6, dc = col & 63;
                    const size_t w0 =
                        ((size_t)(bb * HH + hc) * 64 + dc) * (SS/2) + (s_ >> 1);
                    uint32_t h0, l0, h1, l1;
                    split2(o0, p0v, h0, l0);          // d = dc
                    split2(o1, p1v, h1, l1);          // d = dc+1
                    g_vh[w0] = h0; g_vl[w0] = l0;
                    g_vh[w0 + SS/2] = h1; g_vl[w0 + SS/2] = l1;
                    split2(o2, p2v, h0, l0);          // row+8 -> pair idx +4
                    split2(o3, p3v, h1, l1);
                    g_vh[w0 + 4] = h0; g_vl[w0 + 4] = l0;
                    g_vh[w0 + SS/2 + 4] = h1; g_vl[w0 + SS/2 + 4] = l1;
                }
            }
        }
    } else {
        const float sc = (which == 0) ? 0.125f : 1.0f;
        uint32_t* oh = g_qh[which];
        uint32_t* ol = g_ql[which];
        #pragma unroll
        for (int mt = 0; mt < 4; mt++) {
            const int row = p0 + wm * 64 + mt * 16 + g;
            #pragma unroll
            for (int nn = 0; nn < 4; nn++) {
                const int col = cw + wn * 32 + nn * 8 + 2 * qd;
                const float2 bv = *(const float2*)(bias + col);
                const size_t w0 = (size_t)row * NW + (col >> 1);
                const size_t w1 = (size_t)(row + 8) * NW + (col >> 1);
                split2((c[mt][nn][0] + bv.x) * sc, (c[mt][nn][1] + bv.y) * sc,
                       oh[w0], ol[w0]);
                split2((c[mt][nn][2] + bv.x) * sc, (c[mt][nn][3] + bv.y) * sc,
                       oh[w1], ol[w1]);
            }
        }
    }
}

// ===========================================================================
// Flash attention bf16x3 + ldmatrix (R14 version) + causal tail remap.
// K smem [kpos 64][pitch 36] (dwords); V smem [d 64][pitch 36] (kwords).
// ===========================================================================
#define KPP 36
#define VP  36
#define KSTG (64 * KPP)
#define VSTG (64 * VP)
#define ATTN_SMEM ((2 * 2 * KSTG + 2 * 2 * VSTG) * 4)   // 73728 B

__global__ __launch_bounds__(256, 2) void attn_bf16()
{
    extern __shared__ __align__(16) uint32_t dsm[];
    uint32_t* KH = dsm;                   // [2][64][KPP]
    uint32_t* KL = KH + 2 * KSTG;
    uint32_t* VH = KL + 2 * KSTG;         // [2][64][VP]
    uint32_t* VL = VH + 2 * VSTG;

    const int tid = threadIdx.x, lane = tid & 31, w = tid >> 5;
    const int g = lane >> 2, qd = lane & 3;
    const int qt = (int)gridDim.x - 1 - (int)blockIdx.x;   // longest blocks first
    const int bh = blockIdx.y;
    const int b = bh >> 4, h = bh & 15;
    const int q0 = qt * 128;
    const int kr = tid >> 2, kq = (tid & 3) * 8;    // loader: row, word offset

    const uint32_t dK = smem_u32(KH + kr * KPP + kq);
    const uint32_t dV = smem_u32(VH + kr * VP + kq);
    const size_t vbase = (size_t)(b * HH + h) * 64 * (SS/2);

    auto issue = [&](int kt, int s) {
        const int k0 = kt * 64;
        const size_t rw = (size_t)(b * SS + k0 + kr) * NW + h * 32 + kq;
        const uint32_t ks = dK + s * (KSTG * 4);
        cpa(ks,      g_qh[1] + rw);
        cpa(ks + 16, g_qh[1] + rw + 4);
        cpa(ks + 2 * KSTG * 4,      g_ql[1] + rw);
        cpa(ks + 2 * KSTG * 4 + 16, g_ql[1] + rw + 4);
        const size_t vw = vbase + (size_t)kr * (SS/2) + (k0 >> 1) + kq;
        const uint32_t vs = dV + s * (VSTG * 4);
        cpa(vs,      g_vh + vw);
        cpa(vs + 16, g_vh + vw + 4);
        cpa(vs + 2 * VSTG * 4,      g_vl + vw);
        cpa(vs + 2 * VSTG * 4 + 16, g_vl + vw + 4);
        CP_COMMIT();
    };

    issue(0, 0);

    // ---- Q fragments straight from global ----
    uint32_t qh[4][4], ql[4][4];
    {
        const size_t rw = (size_t)(b * SS + q0 + w * 16 + g) * NW + h * 32;
        const uint32_t* ph = g_qh[0] + rw;
        const uint32_t* pl = g_ql[0] + rw;
        #pragma unroll
        for (int t = 0; t < 4; t++) {
            qh[t][0] = ph[t * 8 + qd];       qh[t][1] = ph[8 * NW + t * 8 + qd];
            qh[t][2] = ph[t * 8 + qd + 4];   qh[t][3] = ph[8 * NW + t * 8 + qd + 4];
            ql[t][0] = pl[t * 8 + qd];       ql[t][1] = pl[8 * NW + t * 8 + qd];
            ql[t][2] = pl[t * 8 + qd + 4];   ql[t][3] = pl[8 * NW + t * 8 + qd + 4];
        }
    }

    // ldmatrix lane constants (shared by K and V frag loads)
    const int lmrow = (lane >> 4) * 8 + (lane & 7);
    const int lmcol = ((lane >> 3) & 1) * 4;
    const uint32_t kBh = smem_u32(KH), kBl = smem_u32(KL);
    const uint32_t vBh = smem_u32(VH), vBl = smem_u32(VL);

    float m0 = -1e30f, m1 = -1e30f, l0s = 0.f, l1s = 0.f;
    float acc[8][4] = {};

    const int nkt = 2 * qt + 2;
    for (int kt = 0; kt < nkt; kt++) {
        const int s = kt & 1;
        const int k0 = kt * 64;
        if (kt + 1 < nkt) { issue(kt + 1, s ^ 1); CP_WAIT1(); }
        else              { CP_WAIT0(); }
        __syncthreads();

        if (k0 <= q0 + w * 16 + 15) {
            // ---- S = Q K^T (Q pre-scaled), 3-term, ldmatrix frags ----
            float c[8][4] = {};
            #pragma unroll
            for (int t = 0; t < 4; t++) {
                #pragma unroll
                for (int p = 0; p < 4; p++) {
                    const uint32_t off = (uint32_t)s * (KSTG * 4) +
                        ((p * 16 + lmrow) * KPP + t * 8 + lmcol) * 4;
                    uint32_t b0, b1, b2, b3, e0, e1, e2, e3;
                    ldsm4(b0, b1, b2, b3, kBh + off);
                    ldsm4(e0, e1, e2, e3, kBl + off);
                    mma16(c[2*p],   qh[t], b0, b1);
                    mma16(c[2*p],   qh[t], e0, e1);
                    mma16(c[2*p],   ql[t], b0, b1);
                    mma16(c[2*p+1], qh[t], b2, b3);
                    mma16(c[2*p+1], qh[t], e2, e3);
                    mma16(c[2*p+1], ql[t], b2, b3);
                }
            }

            // ---- causal mask ----
            if (k0 + 63 > q0 + w * 16) {
                const int qg0 = q0 + w * 16 + g, qg1 = qg0 + 8;
                #pragma unroll
                for (int nt = 0; nt < 8; nt++) {
                    const int c0 = k0 + nt * 8 + 2 * qd;
                    if (c0     > qg0) c[nt][0] = -100000.f;
                    if (c0 + 1 > qg0) c[nt][1] = -100000.f;
                    if (c0     > qg1) c[nt][2] = -100000.f;
                    if (c0 + 1 > qg1) c[nt][3] = -100000.f;
                }
            }

            // ---- online softmax ----
            float rmax0 = -1e30f, rmax1 = -1e30f;
            #pragma unroll
            for (int nt = 0; nt < 8; nt++) {
                rmax0 = fmaxf(rmax0, fmaxf(c[nt][0], c[nt][1]));
                rmax1 = fmaxf(rmax1, fmaxf(c[nt][2], c[nt][3]));
            }
            rmax0 = fmaxf(rmax0, __shfl_xor_sync(0xffffffffu, rmax0, 1));
            rmax0 = fmaxf(rmax0, __shfl_xor_sync(0xffffffffu, rmax0, 2));
            rmax1 = fmaxf(rmax1, __shfl_xor_sync(0xffffffffu, rmax1, 1));
            rmax1 = fmaxf(rmax1, __shfl_xor_sync(0xffffffffu, rmax1, 2));

            const float nm0 = fmaxf(m0, rmax0), nm1 = fmaxf(m1, rmax1);
            const float f0 = __expf(m0 - nm0), f1 = __expf(m1 - nm1);
            float s0 = 0.f, s1 = 0.f;
            #pragma unroll
            for (int nt = 0; nt < 8; nt++) {
                c[nt][0] = __expf(c[nt][0] - nm0); s0 += c[nt][0];
                c[nt][1] = __expf(c[nt][1] - nm0); s0 += c[nt][1];
                c[nt][2] = __expf(c[nt][2] - nm1); s1 += c[nt][2];
                c[nt][3] = __expf(c[nt][3] - nm1); s1 += c[nt][3];
            }
            s0 += __shfl_xor_sync(0xffffffffu, s0, 1);
            s0 += __shfl_xor_sync(0xffffffffu, s0, 2);
            s1 += __shfl_xor_sync(0xffffffffu, s1, 1);
            s1 += __shfl_xor_sync(0xffffffffu, s1, 2);
            l0s = l0s * f0 + s0; l1s = l1s * f1 + s1;
            m0 = nm0; m1 = nm1;
            #pragma unroll
            for (int dt = 0; dt < 8; dt++) {
                acc[dt][0] *= f0; acc[dt][1] *= f0;
                acc[dt][2] *= f1; acc[dt][3] *= f1;
            }

            // ---- PV, 3-term; A-frag = packed C-frag, V frags ldmatrix ----
            #pragma unroll
            for (int t = 0; t < 4; t++) {
                uint32_t ah[4], al[4];
                split2(c[2 * t][0],     c[2 * t][1],     ah[0], al[0]);
                split2(c[2 * t][2],     c[2 * t][3],     ah[1], al[1]);
                split2(c[2 * t + 1][0], c[2 * t + 1][1], ah[2], al[2]);
                split2(c[2 * t + 1][2], c[2 * t + 1][3], ah[3], al[3]);
                #pragma unroll
                for (int p = 0; p < 4; p++) {
                    const uint32_t off = (uint32_t)s * (VSTG * 4) +
                        ((p * 16 + lmrow) * VP + t * 8 + lmcol) * 4;
                    uint32_t b0, b1, b2, b3, e0, e1, e2, e3;
                    ldsm4(b0, b1, b2, b3, vBh + off);
                    ldsm4(e0, e1, e2, e3, vBl + off);
                    mma16(acc[2*p],   ah, b0, b1);
                    mma16(acc[2*p],   ah, e0, e1);
                    mma16(acc[2*p],   al, b0, b1);
                    mma16(acc[2*p+1], ah, b2, b3);
                    mma16(acc[2*p+1], ah, e2, e3);
                    mma16(acc[2*p+1], al, b2, b3);
                }
            }
        }
        __syncthreads();   // all reads of stage s done before re-issue into it
    }

    // ---- normalize + write split hi/lo ----
    const float inv0 = 1.f / l0s, inv1 = 1.f / l1s;
    const size_t r0w = (size_t)(b * SS + q0 + w * 16 + g) * NW + h * 32;
    #pragma unroll
    for (int dt = 0; dt < 8; dt++) {
        const size_t w0 = r0w + dt * 4 + qd;
        const size_t w1 = w0 + 8 * NW;
        split2(acc[dt][0] * inv0, acc[dt][1] * inv0, g_ah[w0], g_al[w0]);
        split2(acc[dt][2] * inv1, acc[dt][3] * inv1, g_ah[w1], g_al[w1]);
    }
}

extern "C" void kernel_launch(void* const* d_in, const int* in_sizes, int n_in,
                              void* d_out, int out_size)
{
    const float* x  = (const float*)d_in[0];
    const float* Qw = (const float*)d_in[1];
    const float* Qb = (const float*)d_in[2];
    const float* Kw = (const float*)d_in[3];
    const float* Kb = (const float*)d_in[4];
    const float* Vw = (const float*)d_in[5];
    const float* Vb = (const float*)d_in[6];
    const float* Ow = (const float*)d_in[7];
    const float* Ob = (const float*)d_in[8];
    float* out = (float*)d_out;

    cudaFuncSetAttribute(attn_bf16,
                         cudaFuncAttributeMaxDynamicSharedMemorySize, ATTN_SMEM);

    prep_x<<<(PP * NW) / 256, 256>>>(x);
    prep_w<<<(4 * NW * DM) / 256, 256>>>(Qw, Kw, Vw, Ow);

    dim3 gq(PP / 128, 24);
    gemm_bf16<<<gq, 256>>>(Qb, Kb, Vb, nullptr, 0);

    dim3 ga(SS / 128, BB * HH);
    attn_bf16<<<ga, 256, ATTN_SMEM>>>();

    dim3 go(PP / 128, DM / 128);
    gemm_bf16<<<go, 256>>>(Ob, nullptr, nullptr, out, 1);
}